// round 14
// baseline (speedup 1.0000x reference)
#include <cuda_runtime.h>
#include <cstdint>

// Persistent scratch. Zero at module load; the LAST warp drains it into d_out
// and resets it, so every graph replay starts clean.
// Layout: [0..3] counts[k][n] (k*2+n), [4..23] incorrect[t][k][n] (4+t*4+k*2+n)
__device__ int      g_acc[24];
__device__ unsigned g_done = 0;

__device__ __forceinline__ void extract4(unsigned long long& w, int* idx) {
    #pragma unroll
    for (int j = 0; j < 4; j++) {
        if (w) { idx[j] = __ffsll((long long)w) - 1; w &= w - 1ull; }
        else     idx[j] = -1;
    }
}

__device__ __forceinline__ float sq8(const float4& a, const float4& c,
                                     const float4& pA, const float4& pB) {
    float d, s;
    d = a.x - pA.x; s  = d * d;
    d = a.y - pA.y; s += d * d;
    d = a.z - pA.z; s += d * d;
    d = a.w - pA.w; s += d * d;
    d = c.x - pB.x; s += d * d;
    d = c.y - pB.y; s += d * d;
    d = c.z - pB.z; s += d * d;
    d = c.w - pB.w; s += d * d;
    return s;
}

// Reduce 4 independent per-lane values across the warp in 6 shuffles.
// Result: every lane holds the FULL sum of the entity it "owns":
//   lanes 0-7 -> v0, 8-15 -> v2, 16-23 -> v1, 24-31 -> v3   (own = b4 + 2*b3)
__device__ __forceinline__ float reduce4x(float v0, float v1, float v2, float v3,
                                          int lane) {
    float x = __shfl_xor_sync(0xffffffffu, (lane & 16) ? v0 : v1, 16);
    float A = ((lane & 16) ? v1 : v0) + x;
    float y = __shfl_xor_sync(0xffffffffu, (lane & 16) ? v2 : v3, 16);
    float B = ((lane & 16) ? v3 : v2) + y;
    float w = __shfl_xor_sync(0xffffffffu, (lane & 8) ? A : B, 8);
    float z = ((lane & 8) ? B : A) + w;
    z += __shfl_xor_sync(0xffffffffu, z, 4);
    z += __shfl_xor_sync(0xffffffffu, z, 2);
    z += __shfl_xor_sync(0xffffffffu, z, 1);
    return z;
}

__global__ __launch_bounds__(128, 4)
void acc_warprow(const float* __restrict__ pred,
                 const float* __restrict__ ev,
                 const int*   __restrict__ emask,
                 float* __restrict__ out, int out_n,
                 unsigned total_warps) {
    const int warp = threadIdx.x >> 5;
    const int lane = threadIdx.x & 31;
    const int wgid = blockIdx.x * 4 + warp;
    const int own  = ((lane & 16) ? 1 : 0) | ((lane & 8) ? 2 : 0);

    #pragma unroll 1
    for (int r = 0; r < 2; r++) {
        const int b = wgid * 2 + r;

        // ---- mask bits ----
        const int* mrow = emask + (size_t)b * 128;
        const unsigned lo = __ballot_sync(0xffffffffu, mrow[lane * 2]      != 0);
        const unsigned hi = __ballot_sync(0xffffffffu, mrow[64 + lane * 2] != 0);
        const unsigned long long mm =
            ((unsigned long long)hi << 32) | (unsigned long long)lo;
        const bool is_known = (mm & 1ull) != 0ull;
        const unsigned long long negbits = (mm != 0ull) ? (mm & (mm - 1ull)) : 0ull;
        const bool has_neg = (negbits != 0ull);

        const float4* p4 = reinterpret_cast<const float4*>(pred + (size_t)b * 256);
        const float4 pA = p4[lane];
        const float4 pB = p4[32 + lane];
        const float4* evb = reinterpret_cast<const float4*>(ev + (size_t)b * 64 * 256);

        // ---- pos row (entity 0): needed only when known ----
        float pos2 = 0.0f;
        if (is_known) {
            float s = sq8(__ldcs(evb + lane), __ldcs(evb + 32 + lane), pA, pB);
            #pragma unroll
            for (int off = 16; off > 0; off >>= 1)
                s += __shfl_xor_sync(0xffffffffu, s, off);
            pos2 = s;
        }

        bool  mnlt = false;       // known&has_neg: exists neg row with d2 < pos2
        float mn2  = 3.0e38f;     // ~known&has_neg: exact min of neg d2

        if (has_neg) {
            unsigned long long work = negbits;
            if (is_known) {
                // ---- early-exit scan: stop at first neg row with d2 < pos2 ----
                while (work && !mnlt) {
                    int idx[4];
                    extract4(work, idx);
                    float4 va[4], vc[4];
                    #pragma unroll
                    for (int j = 0; j < 4; j++)
                        if (idx[j] >= 0) {
                            const float4* row = evb + (size_t)idx[j] * 64;
                            va[j] = __ldcs(row + lane);
                            vc[j] = __ldcs(row + 32 + lane);
                        }
                    float v[4];
                    #pragma unroll
                    for (int j = 0; j < 4; j++)
                        v[j] = (idx[j] >= 0) ? sq8(va[j], vc[j], pA, pB) : 3.0e38f;
                    float z = reduce4x(v[0], v[1], v[2], v[3], lane);
                    mnlt = __any_sync(0xffffffffu,
                                      (idx[own] >= 0) && (z < pos2));
                }
            } else {
                // ---- full scan with double-buffered pipeline ----
                int    idxA[4], idxB[4];
                float4 vaA[4], vcA[4], vaB[4], vcB[4];

                #define LOAD4(IDX, VA, VC)                                      \
                    _Pragma("unroll")                                           \
                    for (int j = 0; j < 4; j++)                                 \
                        if (IDX[j] >= 0) {                                      \
                            const float4* row_ = evb + (size_t)IDX[j] * 64;     \
                            VA[j] = __ldcs(row_ + lane);                        \
                            VC[j] = __ldcs(row_ + 32 + lane);                   \
                        }

                #define REDUCE4(IDX, VA, VC) {                                  \
                    float v0_ = (IDX[0] >= 0) ? sq8(VA[0], VC[0], pA, pB) : 3.0e38f; \
                    float v1_ = (IDX[1] >= 0) ? sq8(VA[1], VC[1], pA, pB) : 3.0e38f; \
                    float v2_ = (IDX[2] >= 0) ? sq8(VA[2], VC[2], pA, pB) : 3.0e38f; \
                    float v3_ = (IDX[3] >= 0) ? sq8(VA[3], VC[3], pA, pB) : 3.0e38f; \
                    float z_  = reduce4x(v0_, v1_, v2_, v3_, lane);             \
                    if (IDX[own] >= 0) mn2 = fminf(mn2, z_);                    \
                }

                extract4(work, idxA);
                LOAD4(idxA, vaA, vcA);
                for (;;) {
                    if (idxA[0] < 0) break;
                    extract4(work, idxB);
                    LOAD4(idxB, vaB, vcB);
                    REDUCE4(idxA, vaA, vcA);
                    if (idxB[0] < 0) break;
                    extract4(work, idxA);
                    LOAD4(idxA, vaA, vcA);
                    REDUCE4(idxB, vaB, vcB);
                }
                #undef LOAD4
                #undef REDUCE4

                // final min across warp (per-lane partial mins)
                #pragma unroll
                for (int off = 16; off > 0; off >>= 1)
                    mn2 = fminf(mn2, __shfl_xor_sync(0xffffffffu, mn2, off));
            }
        }

        // ---- per-row histogram (lane 0) ----
        if (lane == 0) {
            const int cell = (is_known ? 2 : 0) + (has_neg ? 1 : 0);
            atomicAdd(&g_acc[cell], 1);

            // thresholds squared: (0.5,1,1.5,2,3)^2 — monotone in d^2 space
            const float T2[5] = {0.25f, 1.0f, 2.25f, 4.0f, 9.0f};
            #pragma unroll
            for (int t = 0; t < 5; t++) {
                bool flag;
                if (is_known && !has_neg)      flag = (T2[t] < pos2);
                else if (!is_known && has_neg) flag = (mn2 < T2[t]);
                else if (is_known && has_neg)  flag = mnlt || (T2[t] < pos2);
                else                           flag = false;
                if (flag) atomicAdd(&g_acc[4 + t * 4 + cell], 1);
            }
        }
    }

    // ---- last-warp finalize: drain scratch into d_out (float32) and reset ----
    __threadfence();
    unsigned ticket = 0;
    if (lane == 0) ticket = atomicAdd(&g_done, 1u);
    ticket = __shfl_sync(0xffffffffu, ticket, 0);
    if (ticket == total_warps - 1) {
        if (lane < 24) out[lane] = (float)atomicExch(&g_acc[lane], 0);
        for (int i = 24 + lane; i < out_n; i += 32) out[i] = 0.0f;
        __threadfence();
        if (lane == 0) atomicExch(&g_done, 0u);
    }
}

extern "C" void kernel_launch(void* const* d_in, const int* in_sizes, int n_in,
                              void* d_out, int out_size) {
    // Bind inputs by element count: ev largest; pred = ev/64; mask = ev/128
    long long nev = -1; int iev = 0;
    for (int i = 0; i < n_in; i++)
        if ((long long)in_sizes[i] > nev) { nev = in_sizes[i]; iev = i; }
    int ipred = iev, imask = iev;
    for (int i = 0; i < n_in; i++) {
        if (i == iev) continue;
        if ((long long)in_sizes[i] * 64  == nev) ipred = i;
        if ((long long)in_sizes[i] * 128 == nev) imask = i;
    }

    const float* pred  = (const float*)d_in[ipred];
    const float* ev    = (const float*)d_in[iev];
    const int*   emask = (const int*)d_in[imask];

    const int B = (int)(nev / (64 * 256));      // 4096 rows
    const int nwarps  = B / 2;                  // 2 rows per warp
    const int nblocks = nwarps / 4;             // 4 warps per 128-thread CTA

    acc_warprow<<<nblocks, 128>>>(pred, ev, emask, (float*)d_out, out_size,
                                  (unsigned)nwarps);
}

// round 15
// speedup vs baseline: 1.0289x; 1.0289x over previous
#include <cuda_runtime.h>
#include <cstdint>

// Persistent scratch. Zero at module load; the LAST warp drains it into d_out
// and resets it, so every graph replay starts clean.
// Layout: [0..3] counts[k][n] (k*2+n), [4..23] incorrect[t][k][n] (4+t*4+k*2+n)
__device__ int      g_acc[24];
__device__ unsigned g_done = 0;

__device__ __forceinline__ void extract4(unsigned long long& w, int* idx) {
    #pragma unroll
    for (int j = 0; j < 4; j++) {
        if (w) { idx[j] = __ffsll((long long)w) - 1; w &= w - 1ull; }
        else     idx[j] = -1;
    }
}

__device__ __forceinline__ float sq8(const float4& a, const float4& c,
                                     const float4& pA, const float4& pB) {
    float d, s;
    d = a.x - pA.x; s  = d * d;
    d = a.y - pA.y; s += d * d;
    d = a.z - pA.z; s += d * d;
    d = a.w - pA.w; s += d * d;
    d = c.x - pB.x; s += d * d;
    d = c.y - pB.y; s += d * d;
    d = c.z - pB.z; s += d * d;
    d = c.w - pB.w; s += d * d;
    return s;
}

// Reduce 4 independent per-lane values across the warp in 6 shuffles.
// Result: every lane holds the FULL sum of the entity it "owns":
//   lanes 0-7 -> v0, 8-15 -> v2, 16-23 -> v1, 24-31 -> v3   (own = b4 + 2*b3)
__device__ __forceinline__ float reduce4x(float v0, float v1, float v2, float v3,
                                          int lane) {
    float x = __shfl_xor_sync(0xffffffffu, (lane & 16) ? v0 : v1, 16);
    float A = ((lane & 16) ? v1 : v0) + x;
    float y = __shfl_xor_sync(0xffffffffu, (lane & 16) ? v2 : v3, 16);
    float B = ((lane & 16) ? v3 : v2) + y;
    float w = __shfl_xor_sync(0xffffffffu, (lane & 8) ? A : B, 8);
    float z = ((lane & 8) ? B : A) + w;
    z += __shfl_xor_sync(0xffffffffu, z, 4);
    z += __shfl_xor_sync(0xffffffffu, z, 2);
    z += __shfl_xor_sync(0xffffffffu, z, 1);
    return z;
}

__global__ __launch_bounds__(128, 4)
void acc_warprow(const float* __restrict__ pred,
                 const float* __restrict__ ev,
                 const int*   __restrict__ emask,
                 float* __restrict__ out, int out_n,
                 unsigned total_warps) {
    const int warp = threadIdx.x >> 5;
    const int lane = threadIdx.x & 31;
    const int wgid = blockIdx.x * 4 + warp;
    const int own  = ((lane & 16) ? 1 : 0) | ((lane & 8) ? 2 : 0);

    #pragma unroll 1
    for (int r = 0; r < 2; r++) {
        const int b = wgid * 2 + r;

        // ---- mask bits ----
        const int* mrow = emask + (size_t)b * 128;
        const unsigned lo = __ballot_sync(0xffffffffu, mrow[lane * 2]      != 0);
        const unsigned hi = __ballot_sync(0xffffffffu, mrow[64 + lane * 2] != 0);
        const unsigned long long mm =
            ((unsigned long long)hi << 32) | (unsigned long long)lo;
        const bool is_known = (mm & 1ull) != 0ull;
        const unsigned long long negbits = (mm != 0ull) ? (mm & (mm - 1ull)) : 0ull;
        const bool has_neg = (negbits != 0ull);

        const float4* p4 = reinterpret_cast<const float4*>(pred + (size_t)b * 256);
        const float4 pA = p4[lane];
        const float4 pB = p4[32 + lane];
        const float4* evb = reinterpret_cast<const float4*>(ev + (size_t)b * 64 * 256);

        // ---- pos row (entity 0): needed only when known ----
        float pos2 = 0.0f;
        if (is_known) {
            float s = sq8(__ldcs(evb + lane), __ldcs(evb + 32 + lane), pA, pB);
            #pragma unroll
            for (int off = 16; off > 0; off >>= 1)
                s += __shfl_xor_sync(0xffffffffu, s, off);
            pos2 = s;
        }

        bool  mnlt = false;       // known&has_neg: exists neg row with d2 < pos2
        float mn2  = 3.0e38f;     // ~known&has_neg: exact min of neg d2

        if (has_neg) {
            unsigned long long work = negbits;
            if (is_known) {
                // ---- early-exit scan: stop at first neg row with d2 < pos2 ----
                while (work && !mnlt) {
                    int idx[4];
                    extract4(work, idx);
                    float4 va[4], vc[4];
                    #pragma unroll
                    for (int j = 0; j < 4; j++)
                        if (idx[j] >= 0) {
                            const float4* row = evb + (size_t)idx[j] * 64;
                            va[j] = __ldcs(row + lane);
                            vc[j] = __ldcs(row + 32 + lane);
                        }
                    float v[4];
                    #pragma unroll
                    for (int j = 0; j < 4; j++)
                        v[j] = (idx[j] >= 0) ? sq8(va[j], vc[j], pA, pB) : 3.0e38f;
                    float z = reduce4x(v[0], v[1], v[2], v[3], lane);
                    mnlt = __any_sync(0xffffffffu,
                                      (idx[own] >= 0) && (z < pos2));
                }
            } else {
                // ---- full scan with double-buffered pipeline ----
                int    idxA[4], idxB[4];
                float4 vaA[4], vcA[4], vaB[4], vcB[4];

                #define LOAD4(IDX, VA, VC)                                      \
                    _Pragma("unroll")                                           \
                    for (int j = 0; j < 4; j++)                                 \
                        if (IDX[j] >= 0) {                                      \
                            const float4* row_ = evb + (size_t)IDX[j] * 64;     \
                            VA[j] = __ldcs(row_ + lane);                        \
                            VC[j] = __ldcs(row_ + 32 + lane);                   \
                        }

                #define REDUCE4(IDX, VA, VC) {                                  \
                    float v0_ = (IDX[0] >= 0) ? sq8(VA[0], VC[0], pA, pB) : 3.0e38f; \
                    float v1_ = (IDX[1] >= 0) ? sq8(VA[1], VC[1], pA, pB) : 3.0e38f; \
                    float v2_ = (IDX[2] >= 0) ? sq8(VA[2], VC[2], pA, pB) : 3.0e38f; \
                    float v3_ = (IDX[3] >= 0) ? sq8(VA[3], VC[3], pA, pB) : 3.0e38f; \
                    float z_  = reduce4x(v0_, v1_, v2_, v3_, lane);             \
                    if (IDX[own] >= 0) mn2 = fminf(mn2, z_);                    \
                }

                extract4(work, idxA);
                LOAD4(idxA, vaA, vcA);
                for (;;) {
                    if (idxA[0] < 0) break;
                    extract4(work, idxB);
                    LOAD4(idxB, vaB, vcB);
                    REDUCE4(idxA, vaA, vcA);
                    if (idxB[0] < 0) break;
                    extract4(work, idxA);
                    LOAD4(idxA, vaA, vcA);
                    REDUCE4(idxB, vaB, vcB);
                }
                #undef LOAD4
                #undef REDUCE4

                // final min across warp (per-lane partial mins)
                #pragma unroll
                for (int off = 16; off > 0; off >>= 1)
                    mn2 = fminf(mn2, __shfl_xor_sync(0xffffffffu, mn2, off));
            }
        }

        // ---- per-row histogram (lane 0) ----
        if (lane == 0) {
            const int cell = (is_known ? 2 : 0) + (has_neg ? 1 : 0);
            atomicAdd(&g_acc[cell], 1);

            // thresholds squared: (0.5,1,1.5,2,3)^2 — monotone in d^2 space
            const float T2[5] = {0.25f, 1.0f, 2.25f, 4.0f, 9.0f};
            #pragma unroll
            for (int t = 0; t < 5; t++) {
                bool flag;
                if (is_known && !has_neg)      flag = (T2[t] < pos2);
                else if (!is_known && has_neg) flag = (mn2 < T2[t]);
                else if (is_known && has_neg)  flag = mnlt || (T2[t] < pos2);
                else                           flag = false;
                if (flag) atomicAdd(&g_acc[4 + t * 4 + cell], 1);
            }
        }
    }

    // ---- last-warp finalize: drain scratch into d_out (float32) and reset ----
    __threadfence();
    unsigned ticket = 0;
    if (lane == 0) ticket = atomicAdd(&g_done, 1u);
    ticket = __shfl_sync(0xffffffffu, ticket, 0);
    if (ticket == total_warps - 1) {
        if (lane < 24) out[lane] = (float)atomicExch(&g_acc[lane], 0);
        for (int i = 24 + lane; i < out_n; i += 32) out[i] = 0.0f;
        __threadfence();
        if (lane == 0) atomicExch(&g_done, 0u);
    }
}

extern "C" void kernel_launch(void* const* d_in, const int* in_sizes, int n_in,
                              void* d_out, int out_size) {
    // Bind inputs by element count: ev largest; pred = ev/64; mask = ev/128
    long long nev = -1; int iev = 0;
    for (int i = 0; i < n_in; i++)
        if ((long long)in_sizes[i] > nev) { nev = in_sizes[i]; iev = i; }
    int ipred = iev, imask = iev;
    for (int i = 0; i < n_in; i++) {
        if (i == iev) continue;
        if ((long long)in_sizes[i] * 64  == nev) ipred = i;
        if ((long long)in_sizes[i] * 128 == nev) imask = i;
    }

    const float* pred  = (const float*)d_in[ipred];
    const float* ev    = (const float*)d_in[iev];
    const int*   emask = (const int*)d_in[imask];

    const int B = (int)(nev / (64 * 256));      // 4096 rows
    const int nwarps  = B / 2;                  // 2 rows per warp
    const int nblocks = nwarps / 4;             // 4 warps per 128-thread CTA

    acc_warprow<<<nblocks, 128>>>(pred, ev, emask, (float*)d_out, out_size,
                                  (unsigned)nwarps);
}

// round 16
// speedup vs baseline: 1.0921x; 1.0614x over previous
#include <cuda_runtime.h>
#include <cstdint>

// Persistent scratch. Zero at module load; the LAST warp drains it into d_out
// and resets it, so every graph replay starts clean.
// Layout: [0..3] counts[k][n] (k*2+n), [4..23] incorrect[t][k][n] (4+t*4+k*2+n)
__device__ int      g_acc[24];
__device__ unsigned g_done = 0;

__device__ __forceinline__ void extract4(unsigned long long& w, int* idx) {
    #pragma unroll
    for (int j = 0; j < 4; j++) {
        if (w) { idx[j] = __ffsll((long long)w) - 1; w &= w - 1ull; }
        else     idx[j] = -1;
    }
}

__device__ __forceinline__ float sq8(const float4& a, const float4& c,
                                     const float4& pA, const float4& pB) {
    float d, s;
    d = a.x - pA.x; s  = d * d;
    d = a.y - pA.y; s += d * d;
    d = a.z - pA.z; s += d * d;
    d = a.w - pA.w; s += d * d;
    d = c.x - pB.x; s += d * d;
    d = c.y - pB.y; s += d * d;
    d = c.z - pB.z; s += d * d;
    d = c.w - pB.w; s += d * d;
    return s;
}

// Reduce 4 independent per-lane values across the warp in 6 shuffles.
// Result: every lane holds the FULL sum of the entity it "owns":
//   lanes 0-7 -> v0, 8-15 -> v2, 16-23 -> v1, 24-31 -> v3   (own = b4 + 2*b3)
__device__ __forceinline__ float reduce4x(float v0, float v1, float v2, float v3,
                                          int lane) {
    float x = __shfl_xor_sync(0xffffffffu, (lane & 16) ? v0 : v1, 16);
    float A = ((lane & 16) ? v1 : v0) + x;
    float y = __shfl_xor_sync(0xffffffffu, (lane & 16) ? v2 : v3, 16);
    float B = ((lane & 16) ? v3 : v2) + y;
    float w = __shfl_xor_sync(0xffffffffu, (lane & 8) ? A : B, 8);
    float z = ((lane & 8) ? B : A) + w;
    z += __shfl_xor_sync(0xffffffffu, z, 4);
    z += __shfl_xor_sync(0xffffffffu, z, 2);
    z += __shfl_xor_sync(0xffffffffu, z, 1);
    return z;
}

__global__ __launch_bounds__(128, 4)
void acc_warprow(const float* __restrict__ pred,
                 const float* __restrict__ ev,
                 const int*   __restrict__ emask,
                 float* __restrict__ out, int out_n,
                 unsigned total_warps) {
    const int warp = threadIdx.x >> 5;
    const int lane = threadIdx.x & 31;
    const int wgid = blockIdx.x * 4 + warp;
    const int own  = ((lane & 16) ? 1 : 0) | ((lane & 8) ? 2 : 0);

    #pragma unroll 1
    for (int r = 0; r < 2; r++) {
        const int b = wgid * 2 + r;

        // ---- mask bits ----
        const int* mrow = emask + (size_t)b * 128;
        const unsigned lo = __ballot_sync(0xffffffffu, mrow[lane * 2]      != 0);
        const unsigned hi = __ballot_sync(0xffffffffu, mrow[64 + lane * 2] != 0);
        const unsigned long long mm =
            ((unsigned long long)hi << 32) | (unsigned long long)lo;
        const bool is_known = (mm & 1ull) != 0ull;
        const unsigned long long negbits = (mm != 0ull) ? (mm & (mm - 1ull)) : 0ull;
        const bool has_neg = (negbits != 0ull);

        const float4* p4 = reinterpret_cast<const float4*>(pred + (size_t)b * 256);
        const float4 pA = p4[lane];
        const float4 pB = p4[32 + lane];
        const float4* evb = reinterpret_cast<const float4*>(ev + (size_t)b * 64 * 256);

        // ---- pos row (entity 0): needed only when known ----
        float pos2 = 0.0f;
        if (is_known) {
            float s = sq8(__ldcs(evb + lane), __ldcs(evb + 32 + lane), pA, pB);
            #pragma unroll
            for (int off = 16; off > 0; off >>= 1)
                s += __shfl_xor_sync(0xffffffffu, s, off);
            pos2 = s;
        }

        bool  mnlt = false;       // known&has_neg: exists neg row with d2 < pos2
        float mn2  = 3.0e38f;     // ~known&has_neg: exact min of neg d2

        if (has_neg) {
            unsigned long long work = negbits;
            if (is_known) {
                // ---- early-exit scan: stop at first neg row with d2 < pos2 ----
                while (work && !mnlt) {
                    int idx[4];
                    extract4(work, idx);
                    float4 va[4], vc[4];
                    #pragma unroll
                    for (int j = 0; j < 4; j++)
                        if (idx[j] >= 0) {
                            const float4* row = evb + (size_t)idx[j] * 64;
                            va[j] = __ldcs(row + lane);
                            vc[j] = __ldcs(row + 32 + lane);
                        }
                    float v[4];
                    #pragma unroll
                    for (int j = 0; j < 4; j++)
                        v[j] = (idx[j] >= 0) ? sq8(va[j], vc[j], pA, pB) : 3.0e38f;
                    float z = reduce4x(v[0], v[1], v[2], v[3], lane);
                    mnlt = __any_sync(0xffffffffu,
                                      (idx[own] >= 0) && (z < pos2));
                }
            } else {
                // ---- full scan with double-buffered pipeline ----
                int    idxA[4], idxB[4];
                float4 vaA[4], vcA[4], vaB[4], vcB[4];

                #define LOAD4(IDX, VA, VC)                                      \
                    _Pragma("unroll")                                           \
                    for (int j = 0; j < 4; j++)                                 \
                        if (IDX[j] >= 0) {                                      \
                            const float4* row_ = evb + (size_t)IDX[j] * 64;     \
                            VA[j] = __ldcs(row_ + lane);                        \
                            VC[j] = __ldcs(row_ + 32 + lane);                   \
                        }

                #define REDUCE4(IDX, VA, VC) {                                  \
                    float v0_ = (IDX[0] >= 0) ? sq8(VA[0], VC[0], pA, pB) : 3.0e38f; \
                    float v1_ = (IDX[1] >= 0) ? sq8(VA[1], VC[1], pA, pB) : 3.0e38f; \
                    float v2_ = (IDX[2] >= 0) ? sq8(VA[2], VC[2], pA, pB) : 3.0e38f; \
                    float v3_ = (IDX[3] >= 0) ? sq8(VA[3], VC[3], pA, pB) : 3.0e38f; \
                    float z_  = reduce4x(v0_, v1_, v2_, v3_, lane);             \
                    if (IDX[own] >= 0) mn2 = fminf(mn2, z_);                    \
                }

                extract4(work, idxA);
                LOAD4(idxA, vaA, vcA);
                for (;;) {
                    if (idxA[0] < 0) break;
                    extract4(work, idxB);
                    LOAD4(idxB, vaB, vcB);
                    REDUCE4(idxA, vaA, vcA);
                    if (idxB[0] < 0) break;
                    extract4(work, idxA);
                    LOAD4(idxA, vaA, vcA);
                    REDUCE4(idxB, vaB, vcB);
                }
                #undef LOAD4
                #undef REDUCE4

                // final min across warp (per-lane partial mins)
                #pragma unroll
                for (int off = 16; off > 0; off >>= 1)
                    mn2 = fminf(mn2, __shfl_xor_sync(0xffffffffu, mn2, off));
            }
        }

        // ---- per-row histogram (lane 0) ----
        if (lane == 0) {
            const int cell = (is_known ? 2 : 0) + (has_neg ? 1 : 0);
            atomicAdd(&g_acc[cell], 1);

            // thresholds squared: (0.5,1,1.5,2,3)^2 — monotone in d^2 space
            const float T2[5] = {0.25f, 1.0f, 2.25f, 4.0f, 9.0f};
            #pragma unroll
            for (int t = 0; t < 5; t++) {
                bool flag;
                if (is_known && !has_neg)      flag = (T2[t] < pos2);
                else if (!is_known && has_neg) flag = (mn2 < T2[t]);
                else if (is_known && has_neg)  flag = mnlt || (T2[t] < pos2);
                else                           flag = false;
                if (flag) atomicAdd(&g_acc[4 + t * 4 + cell], 1);
            }
        }
    }

    // ---- last-warp finalize: drain scratch into d_out (float32) and reset ----
    __threadfence();
    unsigned ticket = 0;
    if (lane == 0) ticket = atomicAdd(&g_done, 1u);
    ticket = __shfl_sync(0xffffffffu, ticket, 0);
    if (ticket == total_warps - 1) {
        if (lane < 24) out[lane] = (float)atomicExch(&g_acc[lane], 0);
        for (int i = 24 + lane; i < out_n; i += 32) out[i] = 0.0f;
        __threadfence();
        if (lane == 0) atomicExch(&g_done, 0u);
    }
}

extern "C" void kernel_launch(void* const* d_in, const int* in_sizes, int n_in,
                              void* d_out, int out_size) {
    // Bind inputs by element count: ev largest; pred = ev/64; mask = ev/128
    long long nev = -1; int iev = 0;
    for (int i = 0; i < n_in; i++)
        if ((long long)in_sizes[i] > nev) { nev = in_sizes[i]; iev = i; }
    int ipred = iev, imask = iev;
    for (int i = 0; i < n_in; i++) {
        if (i == iev) continue;
        if ((long long)in_sizes[i] * 64  == nev) ipred = i;
        if ((long long)in_sizes[i] * 128 == nev) imask = i;
    }

    const float* pred  = (const float*)d_in[ipred];
    const float* ev    = (const float*)d_in[iev];
    const int*   emask = (const int*)d_in[imask];

    const int B = (int)(nev / (64 * 256));      // 4096 rows
    const int nwarps  = B / 2;                  // 2 rows per warp
    const int nblocks = nwarps / 4;             // 4 warps per 128-thread CTA

    acc_warprow<<<nblocks, 128>>>(pred, ev, emask, (float*)d_out, out_size,
                                  (unsigned)nwarps);
}